// round 5
// baseline (speedup 1.0000x reference)
#include <cuda_runtime.h>
#include <cuda_bf16.h>
#include <mma.h>
#include <cstdint>

using namespace nvcuda;

#define N_VOX 200000
#define PP    65536
#define EPSV  1e-5f

// ---- scratch (__device__ globals; allocation-free rule) ----
__device__ float g_h1[(size_t)N_VOX * 64];
__device__ float g_h2[(size_t)N_VOX * 64];
__device__ __nv_bfloat16 g_wb[27 * 8192];  // [27][2(hi/lo)][64][64] bf16, K-major
__device__ float g_stats[256];
__device__ float g_coef[256];

#define RED4(p, a, b, c, d) \
    asm volatile("red.global.add.v4.f32 [%0], {%1,%2,%3,%4};" \
                 :: "l"(p), "f"(a), "f"(b), "f"(c), "f"(d) : "memory")

// smem layout (bytes):
//   [0,      36864)  sAh bf16 [256][72]
//   [36864,  73728)  sAl bf16 [256][72]
//   [0,      65536)  sD  f32  [256][64]  (reuses A after compute)
//   [73728,  74752)  s_row [256]
//   [74752,  75776)  s_orow[256]
#define DSMEM_BYTES 75776

// ---------------------------------------------------------------------------
template <bool SCATTER>
__global__ __launch_bounds__(256)
void conv_mma_kernel(const float* __restrict__ x,
                     const __nv_bfloat16* __restrict__ wb,
                     const int* __restrict__ in_map,
                     const int* __restrict__ out_map,
                     float* __restrict__ H)
{
    extern __shared__ char sm[];
    __nv_bfloat16* sAh = reinterpret_cast<__nv_bfloat16*>(sm);
    __nv_bfloat16* sAl = sAh + 256 * 72;
    float*         sD  = reinterpret_cast<float*>(sm);
    int*           s_row  = reinterpret_cast<int*>(sm + 73728);
    int*           s_orow = s_row + 256;

    const int t    = threadIdx.x;
    const int w    = t >> 5;
    const int lane = t & 31;
    const int base = blockIdx.x * 256;
    const int ky   = SCATTER ? blockIdx.y : 0;
    const int o    = SCATTER ? (ky < 13 ? ky : ky + 1) : 13;

    if (SCATTER) {
        const size_t kbase = (size_t)ky * PP + base;
        if (__ldg(&in_map[kbase]) >= N_VOX) return;   // sentinel tail-packed tile
        s_row[t]  = __ldg(&in_map[kbase + t]);
        s_orow[t] = __ldg(&out_map[kbase + t]);
    } else {
        s_row[t] = base + t;
    }
    __syncthreads();

    // Gather + bf16 hi/lo split. 16 lanes cover one row (coalesced: 2 rows,
    // 4x128B lines per warp instruction).
    {
        const int rsub = lane >> 4;
        const int c4   = lane & 15;
        const float4* x4 = reinterpret_cast<const float4*>(x);
#pragma unroll
        for (int j = 0; j < 16; j++) {
            const int r   = w * 32 + j * 2 + rsub;
            const int row = s_row[r];
            float4 v = make_float4(0.f, 0.f, 0.f, 0.f);
            if (row < N_VOX) v = x4[(size_t)row * 16 + c4];
            union { __nv_bfloat16 b[4]; uint2 u; } hi, lo;
            hi.b[0] = __float2bfloat16(v.x);
            hi.b[1] = __float2bfloat16(v.y);
            hi.b[2] = __float2bfloat16(v.z);
            hi.b[3] = __float2bfloat16(v.w);
            lo.b[0] = __float2bfloat16(v.x - __bfloat162float(hi.b[0]));
            lo.b[1] = __float2bfloat16(v.y - __bfloat162float(hi.b[1]));
            lo.b[2] = __float2bfloat16(v.z - __bfloat162float(hi.b[2]));
            lo.b[3] = __float2bfloat16(v.w - __bfloat162float(hi.b[3]));
            *reinterpret_cast<uint2*>(sAh + r * 72 + c4 * 4) = hi.u;
            *reinterpret_cast<uint2*>(sAl + r * 72 + c4 * 4) = lo.u;
        }
    }
    __syncthreads();

    // Warp w owns rows [32w, 32w+32) x 64 cols. 3-pass bf16 hi/lo.
    // B fragments come straight from GLOBAL (L1/L2-hot, 16 KB per offset).
    wmma::fragment<wmma::accumulator, 16, 16, 16, float> fd[2][4];
#pragma unroll
    for (int mt = 0; mt < 2; mt++)
#pragma unroll
        for (int nt = 0; nt < 4; nt++) wmma::fill_fragment(fd[mt][nt], 0.f);

    const __nv_bfloat16* Wh = wb + (size_t)o * 8192;
    const __nv_bfloat16* Wl = Wh + 4096;

#pragma unroll
    for (int ks = 0; ks < 4; ks++) {
        wmma::fragment<wmma::matrix_a, 16, 16, 16, __nv_bfloat16, wmma::row_major> fah[2], fal[2];
        wmma::fragment<wmma::matrix_b, 16, 16, 16, __nv_bfloat16, wmma::row_major> fbh[4], fbl[4];
#pragma unroll
        for (int mt = 0; mt < 2; mt++) {
            const int r0 = w * 32 + mt * 16;
            wmma::load_matrix_sync(fah[mt], sAh + r0 * 72 + ks * 16, 72);
            wmma::load_matrix_sync(fal[mt], sAl + r0 * 72 + ks * 16, 72);
        }
#pragma unroll
        for (int nt = 0; nt < 4; nt++) {
            wmma::load_matrix_sync(fbh[nt], Wh + ks * 16 * 64 + nt * 16, 64);
            wmma::load_matrix_sync(fbl[nt], Wl + ks * 16 * 64 + nt * 16, 64);
        }
#pragma unroll
        for (int mt = 0; mt < 2; mt++)
#pragma unroll
            for (int nt = 0; nt < 4; nt++) {
                wmma::mma_sync(fd[mt][nt], fah[mt], fbh[nt], fd[mt][nt]);
                wmma::mma_sync(fd[mt][nt], fah[mt], fbl[nt], fd[mt][nt]);
                wmma::mma_sync(fd[mt][nt], fal[mt], fbh[nt], fd[mt][nt]);
            }
    }

    __syncthreads();   // all warps done reading sA before sD overwrites it
#pragma unroll
    for (int mt = 0; mt < 2; mt++)
#pragma unroll
        for (int nt = 0; nt < 4; nt++)
            wmma::store_matrix_sync(sD + (w * 32 + mt * 16) * 64 + nt * 16,
                                    fd[mt][nt], 64, wmma::mem_row_major);
    __syncthreads();

    // Epilogue: 16 lanes per row (coalesced 256B), red-scatter or direct store.
    {
        const int rsub = lane >> 4;
        const int c4   = lane & 15;
#pragma unroll
        for (int j = 0; j < 16; j++) {
            const int r    = w * 32 + j * 2 + rsub;
            const int orow = SCATTER ? s_orow[r] : s_row[r];
            if (orow < N_VOX) {
                float4 v = *reinterpret_cast<const float4*>(sD + r * 64 + c4 * 4);
                float* d = H + (size_t)orow * 64 + c4 * 4;
                if (SCATTER) RED4(d, v.x, v.y, v.z, v.w);
                else         *reinterpret_cast<float4*>(d) = v;
            }
        }
    }
}

// ---------------------------------------------------------------------------
// W prep: bf16 hi/lo split into [27][2][64][64]
__global__ void wprep_kernel(const float* __restrict__ W)
{
    const int o = blockIdx.x;    // 0..26
    const int t = threadIdx.x;   // 128
    for (int idx = t; idx < 4096; idx += 128) {
        float v = W[(size_t)o * 4096 + idx];
        __nv_bfloat16 hi = __float2bfloat16(v);
        __nv_bfloat16 lo = __float2bfloat16(v - __bfloat162float(hi));
        g_wb[(size_t)o * 8192 + idx]        = hi;
        g_wb[(size_t)o * 8192 + 4096 + idx] = lo;
    }
}

// ---------------------------------------------------------------------------
__global__ void zero_stats_kernel() { g_stats[threadIdx.x] = 0.f; }

__global__ void stats_kernel(const float* __restrict__ h, int statoff)
{
    const int t = threadIdx.x;          // 256
    const int ch = t & 63;
    const int g  = t >> 6;              // 0..3
    float s = 0.f, sq = 0.f;
    for (int row = blockIdx.x * 4 + g; row < N_VOX; row += gridDim.x * 4) {
        float v = h[(size_t)row * 64 + ch];
        s += v; sq = fmaf(v, v, sq);
    }
    __shared__ float sh[2][4][64];
    sh[0][g][ch] = s;
    sh[1][g][ch] = sq;
    __syncthreads();
    if (t < 64) {
        float ss = sh[0][0][t] + sh[0][1][t] + sh[0][2][t] + sh[0][3][t];
        atomicAdd(&g_stats[statoff + t], ss);
    } else if (t < 128) {
        int c = t - 64;
        float qq = sh[1][0][c] + sh[1][1][c] + sh[1][2][c] + sh[1][3][c];
        atomicAdd(&g_stats[statoff + 64 + c], qq);
    }
}

__global__ void finalize_stats_kernel(const float* __restrict__ gamma,
                                      const float* __restrict__ beta,
                                      int statoff, int coefoff)
{
    const int c = threadIdx.x;  // 64
    const float inv_n = 1.0f / (float)N_VOX;
    float mu  = g_stats[statoff + c] * inv_n;
    float var = g_stats[statoff + 64 + c] * inv_n - mu * mu;
    float sc  = gamma[c] * rsqrtf(var + EPSV);
    g_coef[coefoff + c]      = sc;
    g_coef[coefoff + 64 + c] = beta[c] - mu * sc;
}

__global__ void bnrelu_kernel(float* __restrict__ h, int coefoff)
{
    int kk = blockIdx.x * blockDim.x + threadIdx.x;
    if (kk >= N_VOX * 16) return;
    int cb = (kk & 15) * 4;
    float4 v = reinterpret_cast<float4*>(h)[kk];
    float s0 = g_coef[coefoff + cb + 0], b0 = g_coef[coefoff + 64 + cb + 0];
    float s1 = g_coef[coefoff + cb + 1], b1 = g_coef[coefoff + 64 + cb + 1];
    float s2 = g_coef[coefoff + cb + 2], b2 = g_coef[coefoff + 64 + cb + 2];
    float s3 = g_coef[coefoff + cb + 3], b3 = g_coef[coefoff + 64 + cb + 3];
    v.x = fmaxf(fmaf(v.x, s0, b0), 0.f);
    v.y = fmaxf(fmaf(v.y, s1, b1), 0.f);
    v.z = fmaxf(fmaf(v.z, s2, b2), 0.f);
    v.w = fmaxf(fmaf(v.w, s3, b3), 0.f);
    reinterpret_cast<float4*>(h)[kk] = v;
}

__global__ void final_kernel(const float* __restrict__ h2,
                             const float* __restrict__ x,
                             float* __restrict__ out, int coefoff)
{
    int kk = blockIdx.x * blockDim.x + threadIdx.x;
    if (kk >= N_VOX * 16) return;
    int cb = (kk & 15) * 4;
    float4 v = reinterpret_cast<const float4*>(h2)[kk];
    float4 r = reinterpret_cast<const float4*>(x)[kk];
    float s0 = g_coef[coefoff + cb + 0], b0 = g_coef[coefoff + 64 + cb + 0];
    float s1 = g_coef[coefoff + cb + 1], b1 = g_coef[coefoff + 64 + cb + 1];
    float s2 = g_coef[coefoff + cb + 2], b2 = g_coef[coefoff + 64 + cb + 2];
    float s3 = g_coef[coefoff + cb + 3], b3 = g_coef[coefoff + 64 + cb + 3];
    v.x = fmaxf(fmaf(v.x, s0, b0) + r.x, 0.f);
    v.y = fmaxf(fmaf(v.y, s1, b1) + r.y, 0.f);
    v.z = fmaxf(fmaf(v.z, s2, b2) + r.z, 0.f);
    v.w = fmaxf(fmaf(v.w, s3, b3) + r.w, 0.f);
    reinterpret_cast<float4*>(out)[kk] = v;
}

// ---------------------------------------------------------------------------
extern "C" void kernel_launch(void* const* d_in, const int* in_sizes, int n_in,
                              void* d_out, int out_size)
{
    const float* x      = (const float*)d_in[0];
    const float* W1     = (const float*)d_in[1];
    const float* gamma1 = (const float*)d_in[2];
    const float* beta1  = (const float*)d_in[3];
    const float* W2     = (const float*)d_in[4];
    const float* gamma2 = (const float*)d_in[5];
    const float* beta2  = (const float*)d_in[6];
    const int*   in_map = (const int*)d_in[7];
    const int*   out_map= (const int*)d_in[8];
    float*       out    = (float*)d_out;

    float* h1;  cudaGetSymbolAddress((void**)&h1, g_h1);
    float* h2;  cudaGetSymbolAddress((void**)&h2, g_h2);
    __nv_bfloat16* wb;  cudaGetSymbolAddress((void**)&wb, g_wb);

    cudaFuncSetAttribute(conv_mma_kernel<true>,
                         cudaFuncAttributeMaxDynamicSharedMemorySize, DSMEM_BYTES);
    cudaFuncSetAttribute(conv_mma_kernel<false>,
                         cudaFuncAttributeMaxDynamicSharedMemorySize, DSMEM_BYTES);

    const dim3 scat_grid(PP / 256, 26);
    const int  center_blocks = (N_VOX + 255) / 256;
    const int  ew_blocks     = (N_VOX * 16 + 255) / 256;

    zero_stats_kernel<<<1, 256>>>();

    // conv1
    wprep_kernel<<<27, 128>>>(W1);
    conv_mma_kernel<false><<<center_blocks, 256, DSMEM_BYTES>>>(x, wb, nullptr, nullptr, h1);
    conv_mma_kernel<true ><<<scat_grid,     256, DSMEM_BYTES>>>(x, wb, in_map, out_map, h1);
    stats_kernel<<<1024, 256>>>(h1, 0);
    finalize_stats_kernel<<<1, 64>>>(gamma1, beta1, 0, 0);
    bnrelu_kernel<<<ew_blocks, 256>>>(h1, 0);

    // conv2
    wprep_kernel<<<27, 128>>>(W2);
    conv_mma_kernel<false><<<center_blocks, 256, DSMEM_BYTES>>>(h1, wb, nullptr, nullptr, h2);
    conv_mma_kernel<true ><<<scat_grid,     256, DSMEM_BYTES>>>(h1, wb, in_map, out_map, h2);
    stats_kernel<<<1024, 256>>>(h2, 128);
    finalize_stats_kernel<<<1, 64>>>(gamma2, beta2, 128, 128);

    final_kernel<<<ew_blocks, 256>>>(h2, x, out, 128);
}

// round 6
// speedup vs baseline: 2.0378x; 2.0378x over previous
#include <cuda_runtime.h>
#include <cuda_bf16.h>
#include <mma.h>
#include <cstdint>

using namespace nvcuda;

#define N_VOX 200000
#define PP    65536
#define EPSV  1e-5f

// ---- scratch (__device__ globals; allocation-free rule) ----
__device__ float g_h1[(size_t)N_VOX * 64];
__device__ float g_h2[(size_t)N_VOX * 64];
__device__ __nv_bfloat16 g_wb[27 * 9216];  // [27][hi 64x72 | lo 64x72] bf16, padded
__device__ float g_stats[256];
__device__ float g_coef[256];  // [0:64] scale1 [64:128] shift1 [128:192] scale2 [192:256] shift2

#define RED4(p, a, b, c, d) \
    asm volatile("red.global.add.v4.f32 [%0], {%1,%2,%3,%4};" \
                 :: "l"(p), "f"(a), "f"(b), "f"(c), "f"(d) : "memory")

// smem layout (bytes):
//   [0,     18432)  sAh bf16 [128][72]
//   [18432, 36864)  sAl bf16 [128][72]
//   [36864, 55296)  sW  bf16 [hi 64x72 | lo 64x72]
//   [0,     32768)  sD  f32 [128][64]   (reuses A region after compute)
//   [55296, 55808)  s_row [128]
//   [55808, 56320)  s_orow[128]
#define DSMEM_BYTES 56320

// ---------------------------------------------------------------------------
template <bool SCATTER, bool FUSE_BN>
__global__ __launch_bounds__(128, 4)
void conv_mma_kernel(const float* __restrict__ x,
                     const __nv_bfloat16* __restrict__ wb,
                     const int* __restrict__ in_map,
                     const int* __restrict__ out_map,
                     float* __restrict__ H)
{
    extern __shared__ char sm[];
    __nv_bfloat16* sAh = reinterpret_cast<__nv_bfloat16*>(sm);
    __nv_bfloat16* sAl = sAh + 128 * 72;
    __nv_bfloat16* sWh = reinterpret_cast<__nv_bfloat16*>(sm + 36864);
    __nv_bfloat16* sWl = sWh + 64 * 72;
    float*         sD  = reinterpret_cast<float*>(sm);
    int*           s_row  = reinterpret_cast<int*>(sm + 55296);
    int*           s_orow = s_row + 128;

    const int t    = threadIdx.x;
    const int w    = t >> 5;
    const int lane = t & 31;
    const int base = blockIdx.x * 128;
    const int ky   = SCATTER ? blockIdx.y : 0;
    const int o    = SCATTER ? (ky < 13 ? ky : ky + 1) : 13;

    if (SCATTER) {
        const size_t kbase = (size_t)ky * PP + base;
        if (__ldg(&in_map[kbase]) >= N_VOX) return;   // sentinel tail-packed tile
        s_row[t]  = __ldg(&in_map[kbase + t]);
        s_orow[t] = __ldg(&out_map[kbase + t]);
    } else {
        s_row[t] = base + t;
    }

    // Stage W_o (hi+lo, padded stride 72, 18432 B flat copy)
    {
        const uint4* src = reinterpret_cast<const uint4*>(wb + (size_t)o * 9216);
        uint4*       dst = reinterpret_cast<uint4*>(sm + 36864);
#pragma unroll
        for (int i = 0; i < 9; i++) dst[t + i * 128] = src[t + i * 128];
    }
    __syncthreads();

    // Gather (+ optional fused BN1+ReLU) + bf16 hi/lo split.
    // 16 lanes cover one row: coalesced 2 rows / 4x128B lines per warp op.
    {
        const int rsub = lane >> 4;
        const int c4   = lane & 15;
        const float4* x4 = reinterpret_cast<const float4*>(x);
        float s0, s1, s2, s3, b0, b1, b2, b3;
        if (FUSE_BN) {
            const int cb = c4 * 4;
            s0 = g_coef[cb + 0]; b0 = g_coef[64 + cb + 0];
            s1 = g_coef[cb + 1]; b1 = g_coef[64 + cb + 1];
            s2 = g_coef[cb + 2]; b2 = g_coef[64 + cb + 2];
            s3 = g_coef[cb + 3]; b3 = g_coef[64 + cb + 3];
        }
#pragma unroll
        for (int j = 0; j < 16; j++) {
            const int r   = w * 32 + j * 2 + rsub;
            const int row = s_row[r];
            float4 v = make_float4(0.f, 0.f, 0.f, 0.f);
            if (row < N_VOX) v = x4[(size_t)row * 16 + c4];
            if (FUSE_BN) {
                v.x = fmaxf(fmaf(v.x, s0, b0), 0.f);
                v.y = fmaxf(fmaf(v.y, s1, b1), 0.f);
                v.z = fmaxf(fmaf(v.z, s2, b2), 0.f);
                v.w = fmaxf(fmaf(v.w, s3, b3), 0.f);
            }
            union { __nv_bfloat16 b[4]; uint2 u; } hi, lo;
            hi.b[0] = __float2bfloat16(v.x);
            hi.b[1] = __float2bfloat16(v.y);
            hi.b[2] = __float2bfloat16(v.z);
            hi.b[3] = __float2bfloat16(v.w);
            lo.b[0] = __float2bfloat16(v.x - __bfloat162float(hi.b[0]));
            lo.b[1] = __float2bfloat16(v.y - __bfloat162float(hi.b[1]));
            lo.b[2] = __float2bfloat16(v.z - __bfloat162float(hi.b[2]));
            lo.b[3] = __float2bfloat16(v.w - __bfloat162float(hi.b[3]));
            *reinterpret_cast<uint2*>(sAh + r * 72 + c4 * 4) = hi.u;
            *reinterpret_cast<uint2*>(sAl + r * 72 + c4 * 4) = lo.u;
        }
    }
    __syncthreads();

    // Warp w: rows [32w,32w+32) x 64 cols, 3-pass bf16 hi/lo.
    // Loop order keeps B fragments loop-local (register discipline: fd 64 +
    // fa 16 + fb 16 regs live -> 4 CTAs/SM under launch_bounds(128,4)).
    wmma::fragment<wmma::accumulator, 16, 16, 16, float> fd[2][4];
#pragma unroll
    for (int mt = 0; mt < 2; mt++)
#pragma unroll
        for (int nt = 0; nt < 4; nt++) wmma::fill_fragment(fd[mt][nt], 0.f);

#pragma unroll
    for (int ks = 0; ks < 4; ks++) {
#pragma unroll
        for (int mt = 0; mt < 2; mt++) {
            wmma::fragment<wmma::matrix_a, 16, 16, 16, __nv_bfloat16, wmma::row_major> fah, fal;
            const int r0 = w * 32 + mt * 16;
            wmma::load_matrix_sync(fah, sAh + r0 * 72 + ks * 16, 72);
            wmma::load_matrix_sync(fal, sAl + r0 * 72 + ks * 16, 72);
#pragma unroll
            for (int nt = 0; nt < 4; nt++) {
                wmma::fragment<wmma::matrix_b, 16, 16, 16, __nv_bfloat16, wmma::row_major> fbh, fbl;
                wmma::load_matrix_sync(fbh, sWh + ks * 16 * 72 + nt * 16, 72);
                wmma::load_matrix_sync(fbl, sWl + ks * 16 * 72 + nt * 16, 72);
                wmma::mma_sync(fd[mt][nt], fah, fbh, fd[mt][nt]);
                wmma::mma_sync(fd[mt][nt], fah, fbl, fd[mt][nt]);
                wmma::mma_sync(fd[mt][nt], fal, fbh, fd[mt][nt]);
            }
        }
    }

    __syncthreads();   // all warps done reading sA before sD overwrites it
#pragma unroll
    for (int mt = 0; mt < 2; mt++)
#pragma unroll
        for (int nt = 0; nt < 4; nt++)
            wmma::store_matrix_sync(sD + (w * 32 + mt * 16) * 64 + nt * 16,
                                    fd[mt][nt], 64, wmma::mem_row_major);
    __syncthreads();

    // Epilogue: 16 lanes per row (coalesced 256B), red-scatter or direct store.
    {
        const int rsub = lane >> 4;
        const int c4   = lane & 15;
#pragma unroll
        for (int j = 0; j < 16; j++) {
            const int r    = w * 32 + j * 2 + rsub;
            const int orow = SCATTER ? s_orow[r] : s_row[r];
            if (orow < N_VOX) {
                float4 v = *reinterpret_cast<const float4*>(sD + r * 64 + c4 * 4);
                float* d = H + (size_t)orow * 64 + c4 * 4;
                if (SCATTER) RED4(d, v.x, v.y, v.z, v.w);
                else         *reinterpret_cast<float4*>(d) = v;
            }
        }
    }
}

// ---------------------------------------------------------------------------
// W prep: bf16 hi/lo split into padded [27][2][64][72]
__global__ void wprep_kernel(const float* __restrict__ W)
{
    const int o = blockIdx.x;    // 0..26
    const int t = threadIdx.x;   // 128
    for (int idx = t; idx < 4608; idx += 128) {
        const int k = idx / 72, n = idx % 72;
        float v = (n < 64) ? W[(size_t)o * 4096 + k * 64 + n] : 0.f;
        __nv_bfloat16 hi = __float2bfloat16(v);
        __nv_bfloat16 lo = __float2bfloat16(v - __bfloat162float(hi));
        g_wb[(size_t)o * 9216 + idx]        = hi;
        g_wb[(size_t)o * 9216 + 4608 + idx] = lo;
    }
}

// ---------------------------------------------------------------------------
__global__ void zero_stats_kernel() { g_stats[threadIdx.x] = 0.f; }

__global__ void stats_kernel(const float* __restrict__ h, int statoff)
{
    const int t = threadIdx.x;          // 256
    const int ch = t & 63;
    const int g  = t >> 6;              // 0..3
    float s = 0.f, sq = 0.f;
    for (int row = blockIdx.x * 4 + g; row < N_VOX; row += gridDim.x * 4) {
        float v = h[(size_t)row * 64 + ch];
        s += v; sq = fmaf(v, v, sq);
    }
    __shared__ float sh[2][4][64];
    sh[0][g][ch] = s;
    sh[1][g][ch] = sq;
    __syncthreads();
    if (t < 64) {
        float ss = sh[0][0][t] + sh[0][1][t] + sh[0][2][t] + sh[0][3][t];
        atomicAdd(&g_stats[statoff + t], ss);
    } else if (t < 128) {
        int c = t - 64;
        float qq = sh[1][0][c] + sh[1][1][c] + sh[1][2][c] + sh[1][3][c];
        atomicAdd(&g_stats[statoff + 64 + c], qq);
    }
}

__global__ void finalize_stats_kernel(const float* __restrict__ gamma,
                                      const float* __restrict__ beta,
                                      int statoff, int coefoff)
{
    const int c = threadIdx.x;  // 64
    const float inv_n = 1.0f / (float)N_VOX;
    float mu  = g_stats[statoff + c] * inv_n;
    float var = g_stats[statoff + 64 + c] * inv_n - mu * mu;
    float sc  = gamma[c] * rsqrtf(var + EPSV);
    g_coef[coefoff + c]      = sc;
    g_coef[coefoff + 64 + c] = beta[c] - mu * sc;
}

// out = relu(bn2(h2) + x)
__global__ void final_kernel(const float* __restrict__ h2,
                             const float* __restrict__ x,
                             float* __restrict__ out, int coefoff)
{
    int kk = blockIdx.x * blockDim.x + threadIdx.x;
    if (kk >= N_VOX * 16) return;
    int cb = (kk & 15) * 4;
    float4 v = reinterpret_cast<const float4*>(h2)[kk];
    float4 r = reinterpret_cast<const float4*>(x)[kk];
    float s0 = g_coef[coefoff + cb + 0], b0 = g_coef[coefoff + 64 + cb + 0];
    float s1 = g_coef[coefoff + cb + 1], b1 = g_coef[coefoff + 64 + cb + 1];
    float s2 = g_coef[coefoff + cb + 2], b2 = g_coef[coefoff + 64 + cb + 2];
    float s3 = g_coef[coefoff + cb + 3], b3 = g_coef[coefoff + 64 + cb + 3];
    v.x = fmaxf(fmaf(v.x, s0, b0) + r.x, 0.f);
    v.y = fmaxf(fmaf(v.y, s1, b1) + r.y, 0.f);
    v.z = fmaxf(fmaf(v.z, s2, b2) + r.z, 0.f);
    v.w = fmaxf(fmaf(v.w, s3, b3) + r.w, 0.f);
    reinterpret_cast<float4*>(out)[kk] = v;
}

// ---------------------------------------------------------------------------
extern "C" void kernel_launch(void* const* d_in, const int* in_sizes, int n_in,
                              void* d_out, int out_size)
{
    const float* x      = (const float*)d_in[0];
    const float* W1     = (const float*)d_in[1];
    const float* gamma1 = (const float*)d_in[2];
    const float* beta1  = (const float*)d_in[3];
    const float* W2     = (const float*)d_in[4];
    const float* gamma2 = (const float*)d_in[5];
    const float* beta2  = (const float*)d_in[6];
    const int*   in_map = (const int*)d_in[7];
    const int*   out_map= (const int*)d_in[8];
    float*       out    = (float*)d_out;

    float* h1;  cudaGetSymbolAddress((void**)&h1, g_h1);
    float* h2;  cudaGetSymbolAddress((void**)&h2, g_h2);
    __nv_bfloat16* wb;  cudaGetSymbolAddress((void**)&wb, g_wb);

    cudaFuncSetAttribute(conv_mma_kernel<true, false>,
                         cudaFuncAttributeMaxDynamicSharedMemorySize, DSMEM_BYTES);
    cudaFuncSetAttribute(conv_mma_kernel<false, false>,
                         cudaFuncAttributeMaxDynamicSharedMemorySize, DSMEM_BYTES);
    cudaFuncSetAttribute(conv_mma_kernel<true, true>,
                         cudaFuncAttributeMaxDynamicSharedMemorySize, DSMEM_BYTES);
    cudaFuncSetAttribute(conv_mma_kernel<false, true>,
                         cudaFuncAttributeMaxDynamicSharedMemorySize, DSMEM_BYTES);

    const dim3 scat_grid(PP / 128, 26);
    const int  center_blocks = (N_VOX + 127) / 128;
    const int  ew_blocks     = (N_VOX * 16 + 255) / 256;

    zero_stats_kernel<<<1, 256>>>();

    // conv1 (raw x)
    wprep_kernel<<<27, 128>>>(W1);
    conv_mma_kernel<false, false><<<center_blocks, 128, DSMEM_BYTES>>>(x, wb, nullptr, nullptr, h1);
    conv_mma_kernel<true,  false><<<scat_grid,     128, DSMEM_BYTES>>>(x, wb, in_map, out_map, h1);
    stats_kernel<<<1024, 256>>>(h1, 0);
    finalize_stats_kernel<<<1, 64>>>(gamma1, beta1, 0, 0);

    // conv2: BN1+ReLU fused into the gather (h1 stays raw)
    wprep_kernel<<<27, 128>>>(W2);
    conv_mma_kernel<false, true><<<center_blocks, 128, DSMEM_BYTES>>>(h1, wb, nullptr, nullptr, h2);
    conv_mma_kernel<true,  true><<<scat_grid,     128, DSMEM_BYTES>>>(h1, wb, in_map, out_map, h2);
    stats_kernel<<<1024, 256>>>(h2, 128);
    finalize_stats_kernel<<<1, 64>>>(gamma2, beta2, 128, 128);

    // bn2 + residual + relu -> d_out
    final_kernel<<<ew_blocks, 256>>>(h2, x, out, 128);
}